// round 1
// baseline (speedup 1.0000x reference)
#include <cuda_runtime.h>
#include <cuda_bf16.h>

// BumpX: out[b,l,f] = sum_g mask(g-f, aa[b,l,f]) * x[b,l,g] / sum_g mask(...)
// mask(d, a) = 1 - gg((d^2 - a^2)/((a+3)^2 - a^2)),  gg(t) = ff(t)/(ff(t)+ff(1-t)),
// ff(t) = exp(-1/max(softplus(t), 1e-6)).
//
// Key facts:
//   * denominator (a+3)^2 - a^2 = 6a + 9, a in [0,1) -> in [9,15).
//   * arg >= 0 for all |d| >= 1 and monotone increasing in |d|.
//   * mask = 1/(1 + exp(1/v - 1/u)), u = clamp(softplus(arg)), v = clamp(softplus(1-arg)).
//   * for |d| >= 10: 1/v > 270 -> exp overflows to +inf in fp32 -> mask == 0.0f exactly.
// So a window |d| <= 10 reproduces the dense fp32 result bit-for-negligibly.

#define BX_F   1024
#define BX_W   10          // window half-width; mask is exactly 0 (fp32) beyond this
#define BX_TPB 256         // threads per block = f-chunk size

__device__ __forceinline__ float bx_softplus(float t) {
    // numerically stable softplus: max(t,0) + log(1 + exp(-|t|))
    float e = __expf(-fabsf(t));
    return fmaxf(t, 0.0f) + __logf(1.0f + e);
}

__global__ __launch_bounds__(BX_TPB)
void BumpX_kernel(const float* __restrict__ x,
                  const float* __restrict__ aa,
                  float* __restrict__ out)
{
    // blockIdx.x encodes (row, f-chunk): 4 chunks of 256 per row of F=1024
    const int row   = blockIdx.x >> 2;        // b*L + l
    const int fbase = (blockIdx.x & 3) * BX_TPB;

    __shared__ float sx[BX_TPB + 2 * BX_W];

    const float* xr = x + row * BX_F;

    // stage x[fbase-W .. fbase+TPB+W) with zero padding outside [0, F)
    for (int i = threadIdx.x; i < BX_TPB + 2 * BX_W; i += BX_TPB) {
        int g = fbase - BX_W + i;
        sx[i] = (g >= 0 && g < BX_F) ? xr[g] : 0.0f;
    }
    __syncthreads();

    const int f = fbase + (int)threadIdx.x;
    const float a       = aa[row * BX_F + f];
    const float a2      = a * a;
    const float inv_den = 1.0f / fmaf(6.0f, a, 9.0f);   // 1/(6a+9)

    float ws  = 0.0f;   // weighted sum
    float den = 0.0f;   // mask sum

    #pragma unroll
    for (int d = -BX_W; d <= BX_W; ++d) {
        const int g = f + d;
        const float dd  = (float)(d * d);
        const float arg = (dd - a2) * inv_den;

        float u = fmaxf(bx_softplus(arg),        1e-6f);
        float v = fmaxf(bx_softplus(1.0f - arg), 1e-6f);
        // mask = ff(1-arg) / (ff(arg) + ff(1-arg)) = 1 / (1 + exp(1/v - 1/u))
        float m = 1.0f / (1.0f + __expf(__frcp_rn(v) - __frcp_rn(u)));

        if (g >= 0 && g < BX_F) {
            ws  = fmaf(m, sx[threadIdx.x + BX_W + d], ws);
            den += m;
        }
    }

    out[row * BX_F + f] = ws / den;
}

extern "C" void kernel_launch(void* const* d_in, const int* in_sizes, int n_in,
                              void* d_out, int out_size)
{
    const float* x  = (const float*)d_in[0];
    const float* aa = (const float*)d_in[1];
    float* out      = (float*)d_out;

    const int rows = out_size / BX_F;          // B*L = 128
    dim3 grid(rows * (BX_F / BX_TPB));         // 512 blocks
    BumpX_kernel<<<grid, BX_TPB>>>(x, aa, out);
}

// round 2
// speedup vs baseline: 1.2191x; 1.2191x over previous
#include <cuda_runtime.h>
#include <cuda_bf16.h>

// BumpX: out[b,l,f] = sum_g mask(g-f, aa[b,l,f]) * x[b,l,g] / sum_g mask(...)
// mask(d, a) = 1 - gg((d^2 - a^2)/(6a + 9)),  gg(t) = ff(t)/(ff(t)+ff(1-t)),
// ff(t) = exp(-1/max(softplus(t), 1e-6)).
//
// Facts exploited:
//   * mask == 1/(1 + exp(1/v - 1/u)), u = softplus(arg), v = softplus(1-arg).
//   * arg depends on d^2 only  ->  mask(+d) == mask(-d) bitwise. 11 masks, not 21.
//   * for |d| >= 10 the exp overflows to +inf in fp32 -> mask == 0 exactly,
//     so the |d| <= 10 window reproduces the dense fp32 result.
//   * clamps never bind: u >= softplus(-1/15) > 0.64; v >= softplus(1-100/9) ~ 4e-5 > 1e-6.

#define BX_F   1024
#define BX_W   10
#define BX_TPB 128

__device__ __forceinline__ float bx_softplus(float t) {
    // stable softplus: max(t,0) + log(1 + exp(-|t|))
    float e = __expf(-fabsf(t));
    return fmaxf(t, 0.0f) + __logf(1.0f + e);
}

__device__ __forceinline__ float bx_mask(float arg) {
    float u = bx_softplus(arg);
    float v = bx_softplus(1.0f - arg);
    // 1/(1 + exp(1/v - 1/u)); exp->inf gives exactly 0, exp->0 gives exactly 1
    return __frcp_rn(1.0f + __expf(__frcp_rn(v) - __frcp_rn(u)));
}

__global__ __launch_bounds__(BX_TPB)
void BumpX_kernel(const float* __restrict__ x,
                  const float* __restrict__ aa,
                  float* __restrict__ out)
{
    // blockIdx.x encodes (row, f-chunk): 8 chunks of 128 per row of F=1024
    const int row   = blockIdx.x >> 3;                 // b*L + l
    const int fbase = (blockIdx.x & 7) * BX_TPB;

    __shared__ float sx[BX_TPB + 2 * BX_W];

    const float* xr = x + row * BX_F;

    // stage x[fbase-W .. fbase+TPB+W) with zero padding outside [0, F)
    for (int i = threadIdx.x; i < BX_TPB + 2 * BX_W; i += BX_TPB) {
        int g = fbase - BX_W + i;
        sx[i] = (g >= 0 && g < BX_F) ? xr[g] : 0.0f;
    }
    __syncthreads();

    const int f = fbase + (int)threadIdx.x;
    const float a       = aa[row * BX_F + f];
    const float inv_den = __frcp_rn(fmaf(6.0f, a, 9.0f));   // 1/(6a+9)
    const float c0      = a * a * inv_den;                   // a^2/(6a+9)

    const int ci = (int)threadIdx.x + BX_W;   // center index in sx

    // d = 0 tap (always in range)
    float m0  = bx_mask(-c0);
    float ws  = m0 * sx[ci];
    float den = m0;

    #pragma unroll
    for (int d = 1; d <= BX_W; ++d) {
        const float arg = fmaf((float)(d * d), inv_den, -c0);
        const float m   = bx_mask(arg);
        // weighted sum: halo is zero-padded, both sides safe
        ws = fmaf(m, sx[ci - d] + sx[ci + d], ws);
        // denominator: count only in-range taps
        const float cnt = (float)((f >= d) + (f + d < BX_F));
        den = fmaf(m, cnt, den);
    }

    out[row * BX_F + f] = ws * __frcp_rn(den);
}

extern "C" void kernel_launch(void* const* d_in, const int* in_sizes, int n_in,
                              void* d_out, int out_size)
{
    const float* x  = (const float*)d_in[0];
    const float* aa = (const float*)d_in[1];
    float* out      = (float*)d_out;

    const int rows = out_size / BX_F;                  // B*L = 128
    dim3 grid(rows * (BX_F / BX_TPB));                 // 1024 blocks
    BumpX_kernel<<<grid, BX_TPB>>>(x, aa, out);
}

// round 3
// speedup vs baseline: 1.4007x; 1.1489x over previous
#include <cuda_runtime.h>
#include <cuda_bf16.h>

// BumpX: out[b,l,f] = sum_g mask(g-f, aa[b,l,f]) * x[b,l,g] / sum_g mask(...)
// mask(d, a) = 1 - gg((d^2 - a^2)/(6a + 9)),  gg(t) = ff(t)/(ff(t)+ff(1-t)),
// ff(t) = exp(-1/max(softplus(t), 1e-6)).
//
// Exploited facts:
//   * mask = 1/(1 + exp(1/v - 1/u)), u = softplus(arg), v = softplus(1-arg);
//     1/v - 1/u == (u-v) * rcp(u*v)  (one MUFU.RCP saved; same saturation:
//     q -> +big => exp -> inf => mask == 0 exactly).
//   * arg depends on d^2 only -> mask(+d) == mask(-d) bitwise.
//   * worst case (a->1): mask(d=8) <= 4e-11, mask(d=9) <= 3e-34 -> W=8 window
//     is numerically indistinguishable from the dense fp32 computation.
//   * clamps at 1e-6 never bind inside the window.
//
// Parallelization: 2 threads per output (tap-parity split) to double warps/SM
// (latency-bound kernel, occ was 37%); combine partials with one shfl_xor.

#define BX_F   1024
#define BX_W   8
#define BX_OPB 64          // outputs per block
#define BX_TPB 128         // 2 threads per output

__device__ __forceinline__ float bx_softplus(float t) {
    // stable softplus: max(t,0) + log(1 + exp(-|t|))
    float e = __expf(-fabsf(t));
    return fmaxf(t, 0.0f) + __logf(1.0f + e);
}

__device__ __forceinline__ float bx_mask(float arg) {
    float u = bx_softplus(arg);
    float v = bx_softplus(1.0f - arg);
    float q = (u - v) * __frcp_rn(u * v);      // == 1/v - 1/u
    return __frcp_rn(1.0f + __expf(q));
}

__global__ __launch_bounds__(BX_TPB)
void BumpX_kernel(const float* __restrict__ x,
                  const float* __restrict__ aa,
                  float* __restrict__ out)
{
    // blockIdx.x encodes (row, f-chunk): 16 chunks of 64 per row of F=1024
    const int row   = blockIdx.x >> 4;                 // b*L + l
    const int fbase = (blockIdx.x & 15) * BX_OPB;

    __shared__ float sx[BX_OPB + 2 * BX_W];            // 80 floats

    const float* xr = x + row * BX_F;

    // stage x[fbase-W .. fbase+OPB+W) with zero padding outside [0, F)
    for (int i = threadIdx.x; i < BX_OPB + 2 * BX_W; i += BX_TPB) {
        int g = fbase - BX_W + i;
        sx[i] = (g >= 0 && g < BX_F) ? xr[g] : 0.0f;
    }
    __syncthreads();

    const int o = (int)threadIdx.x >> 1;   // output within block
    const int h = (int)threadIdx.x & 1;    // tap-parity half

    const int f = fbase + o;
    const float a       = aa[row * BX_F + f];
    const float inv_den = __frcp_rn(fmaf(6.0f, a, 9.0f));   // 1/(6a+9)
    const float c0      = a * a * inv_den;                   // a^2/(6a+9)

    const int ci = o + BX_W;               // center index in sx

    float ws  = 0.0f;
    float den = 0.0f;

    if (h == 0) {                          // d = 0 tap
        float m0 = bx_mask(-c0);
        ws  = m0 * sx[ci];
        den = m0;
    }

    // h==0 handles d = 2,4,6,8 ; h==1 handles d = 1,3,5,7
    #pragma unroll
    for (int k = 0; k < 4; ++k) {
        const int d = 2 * k + 2 - h;
        const float arg = fmaf((float)(d * d), inv_den, -c0);
        const float m   = bx_mask(arg);
        ws = fmaf(m, sx[ci - d] + sx[ci + d], ws);           // halo zero-padded
        const float cnt = (float)((f >= d) + (f + d < BX_F)); // in-range taps
        den = fmaf(m, cnt, den);
    }

    // combine tap-parity halves
    ws  += __shfl_xor_sync(0xFFFFFFFFu, ws,  1);
    den += __shfl_xor_sync(0xFFFFFFFFu, den, 1);

    if (h == 0)
        out[row * BX_F + f] = ws * __frcp_rn(den);
}

extern "C" void kernel_launch(void* const* d_in, const int* in_sizes, int n_in,
                              void* d_out, int out_size)
{
    const float* x  = (const float*)d_in[0];
    const float* aa = (const float*)d_in[1];
    float* out      = (float*)d_out;

    const int rows = out_size / BX_F;                  // B*L = 128
    dim3 grid(rows * (BX_F / BX_OPB));                 // 2048 blocks
    BumpX_kernel<<<grid, BX_TPB>>>(x, aa, out);
}

// round 4
// speedup vs baseline: 1.5019x; 1.0722x over previous
#include <cuda_runtime.h>
#include <cuda_bf16.h>

// BumpX: out[b,l,f] = sum_g mask(g-f, aa[b,l,f]) * x[b,l,g] / sum_g mask(...)
// mask(d,a) = 1 - gg((d^2 - a^2)/(6a+9)), gg(t)=ff(t)/(ff(t)+ff(1-t)),
// ff(t)=exp(-1/clamp(softplus(t),1e-6)).
//
// Exploited facts:
//   * mask = 1/(1 + exp(1/v - 1/u)), u=softplus(arg), v=softplus(1-arg);
//     symmetric in d -> 1 mask per |d|.
//   * W=6 window: worst-case dropped tap (d=7, a->1) has mask ~7e-5, giving
//     <= ~1e-4 worst-case relative output error vs the 1e-3 gate.
//   * with W=6, arg in [-0.12, 4.0]: no overflow, clamps never bind -> use the
//     raw log2-domain softplus (no fabs/fmax/stability dance):
//       L(t) = log2(1 + 2^(t*log2e)) = softplus(t)/ln2
//       1/v - 1/u = log2e*(Lu - Lv)/(Lu*Lv)
//       mask = 1/(1 + 2^( log2e^2 * (Lu-Lv) * rcp(Lu*Lv) ))
//   * 2 threads per output (tap-parity split) for occupancy; shfl_xor combine.
//   * interior f-chunks (14/16 per row) skip all boundary predicates.

#define BX_F    1024
#define BX_W    6
#define BX_OPB  64          // outputs per block
#define BX_TPB  128         // 2 threads per output
#define BX_L2E  1.4426950408889634f
#define BX_L2E2 2.0813689810056077f   // log2e^2

__device__ __forceinline__ float bx_mask(float a1) {
    // a1 = arg * log2e ; a2 = (1-arg) * log2e
    float a2 = BX_L2E - a1;
    float Lu = __log2f(1.0f + exp2f(a1));
    float Lv = __log2f(1.0f + exp2f(a2));
    float q  = (Lu - Lv) * __frcp_rn(Lu * Lv);
    float E  = exp2f(BX_L2E2 * q);
    return __frcp_rn(1.0f + E);
}

template <bool INTERIOR>
__device__ __forceinline__ void bx_body(const float* __restrict__ aa,
                                        float* __restrict__ out,
                                        const float* sx,
                                        int row, int fbase)
{
    const int o = (int)threadIdx.x >> 1;   // output within block
    const int h = (int)threadIdx.x & 1;    // tap-parity half

    const int f = fbase + o;
    const float a        = aa[row * BX_F + f];
    const float inv_den2 = BX_L2E * __frcp_rn(fmaf(6.0f, a, 9.0f));
    const float c02      = a * a * inv_den2;   // (a^2/(6a+9)) * log2e

    const int ci = o + BX_W;               // center index in sx

    float ws = 0.0f;    // weighted sum (this half)
    float sm = 0.0f;    // sum of masks for d >= 1 (this half)
    float m0 = 0.0f;    // center mask (h==0 only)
    float dn = 0.0f;    // boundary-path denominator

    if (h == 0) {                          // d = 0 tap
        m0 = bx_mask(-c02);
        ws = m0 * sx[ci];
    }

    // h==0 handles d = 2,4,6 ; h==1 handles d = 1,3,5
    #pragma unroll
    for (int k = 0; k < 3; ++k) {
        const int d = 2 * k + 2 - h;
        const float a1 = fmaf((float)(d * d), inv_den2, -c02);
        const float m  = bx_mask(a1);
        ws = fmaf(m, sx[ci - d] + sx[ci + d], ws);   // halo zero-padded
        if (INTERIOR) {
            sm += m;
        } else {
            const float cnt = (float)((f >= d) + (f + d < BX_F));
            dn = fmaf(m, cnt, dn);
        }
    }

    float den = INTERIOR ? fmaf(2.0f, sm, m0) : (dn + m0);

    // combine tap-parity halves
    ws  += __shfl_xor_sync(0xFFFFFFFFu, ws,  1);
    den += __shfl_xor_sync(0xFFFFFFFFu, den, 1);

    if (h == 0)
        out[row * BX_F + f] = ws * __frcp_rn(den);
}

__global__ __launch_bounds__(BX_TPB)
void BumpX_kernel(const float* __restrict__ x,
                  const float* __restrict__ aa,
                  float* __restrict__ out)
{
    // blockIdx.x encodes (row, f-chunk): 16 chunks of 64 per row of F=1024
    const int row   = blockIdx.x >> 4;                 // b*L + l
    const int chunk = blockIdx.x & 15;
    const int fbase = chunk * BX_OPB;

    __shared__ float sx[BX_OPB + 2 * BX_W];            // 76 floats

    const float* xr = x + row * BX_F;

    // stage x[fbase-W .. fbase+OPB+W) with zero padding outside [0, F)
    for (int i = threadIdx.x; i < BX_OPB + 2 * BX_W; i += BX_TPB) {
        int g = fbase - BX_W + i;
        sx[i] = (g >= 0 && g < BX_F) ? xr[g] : 0.0f;
    }
    __syncthreads();

    if (chunk != 0 && chunk != 15)
        bx_body<true>(aa, out, sx, row, fbase);
    else
        bx_body<false>(aa, out, sx, row, fbase);
}

extern "C" void kernel_launch(void* const* d_in, const int* in_sizes, int n_in,
                              void* d_out, int out_size)
{
    const float* x  = (const float*)d_in[0];
    const float* aa = (const float*)d_in[1];
    float* out      = (float*)d_out;

    const int rows = out_size / BX_F;                  // B*L = 128
    dim3 grid(rows * (BX_F / BX_OPB));                 // 2048 blocks
    BumpX_kernel<<<grid, BX_TPB>>>(x, aa, out);
}

// round 5
// speedup vs baseline: 1.5551x; 1.0354x over previous
#include <cuda_runtime.h>
#include <cuda_bf16.h>

// BumpX: out[b,l,f] = sum_g mask(g-f, aa[b,l,f]) * x[b,l,g] / sum_g mask(...)
// mask(d,a) = 1 - gg((d^2 - a^2)/(6a+9)), gg(t)=ff(t)/(ff(t)+ff(1-t)),
// ff(t)=exp(-1/clamp(softplus(t),1e-6)).
//
// Exploited facts:
//   * mask = 1/(1 + exp(1/v - 1/u)), u=softplus(arg), v=softplus(1-arg);
//     symmetric in d -> 1 mask per |d|.
//   * W=6 window: worst-case dropped tap (d=7) has mask ~7e-5 -> <=~1e-4
//     worst-case relative output error vs the 1e-3 gate.
//   * with W=6, arg in [-0.12, 4.0]: no overflow, clamps never bind ->
//     log2-domain softplus: L(t) = log2(1+2^(t*log2e)) = softplus(t)/ln2,
//     1/v - 1/u = log2e*(Lu-Lv)/(Lu*Lv),
//     mask = 1/(1 + 2^( log2e^2 * (Lu-Lv) * rcp(Lu*Lv) )).
//   * ALL transcendentals forced to single-MUFU SASS via inline PTX
//     (ex2/lg2/rcp .approx.ftz) — plain exp2f / __frcp_rn can expand to
//     multi-instruction accurate paths depending on compile flags, which
//     was inflating issue slots in earlier rounds.
//   * 2 threads per output (tap-parity split); shfl_xor combine.
//   * interior f-chunks (14/16 per row) skip boundary predicates.

#define BX_F    1024
#define BX_W    6
#define BX_OPB  64          // outputs per block
#define BX_TPB  128         // 2 threads per output
#define BX_L2E  1.4426950408889634f
#define BX_L2E2 2.0813689810056077f   // log2e^2

__device__ __forceinline__ float bx_ex2(float x) {
    float r;
    asm("ex2.approx.ftz.f32 %0, %1;" : "=f"(r) : "f"(x));
    return r;
}
__device__ __forceinline__ float bx_lg2(float x) {
    float r;
    asm("lg2.approx.ftz.f32 %0, %1;" : "=f"(r) : "f"(x));
    return r;
}
__device__ __forceinline__ float bx_rcp(float x) {
    float r;
    asm("rcp.approx.ftz.f32 %0, %1;" : "=f"(r) : "f"(x));
    return r;
}

__device__ __forceinline__ float bx_mask(float a1) {
    // a1 = arg * log2e ; a2 = (1-arg) * log2e
    float a2 = BX_L2E - a1;
    float Lu = bx_lg2(1.0f + bx_ex2(a1));
    float Lv = bx_lg2(1.0f + bx_ex2(a2));
    float q  = (Lu - Lv) * bx_rcp(Lu * Lv);
    float E  = bx_ex2(BX_L2E2 * q);
    return bx_rcp(1.0f + E);
}

template <bool INTERIOR>
__device__ __forceinline__ void bx_body(const float* __restrict__ aa,
                                        float* __restrict__ out,
                                        const float* sx,
                                        int row, int fbase)
{
    const int o = (int)threadIdx.x >> 1;   // output within block
    const int h = (int)threadIdx.x & 1;    // tap-parity half

    const int f = fbase + o;
    const float a        = aa[row * BX_F + f];
    const float inv_den2 = BX_L2E * bx_rcp(fmaf(6.0f, a, 9.0f));
    const float c02      = a * a * inv_den2;   // (a^2/(6a+9)) * log2e

    const int ci = o + BX_W;               // center index in sx

    float ws = 0.0f;    // weighted sum (this half)
    float sm = 0.0f;    // sum of masks for d >= 1 (this half)
    float m0 = 0.0f;    // center mask (h==0 only)
    float dn = 0.0f;    // boundary-path denominator

    if (h == 0) {                          // d = 0 tap
        m0 = bx_mask(-c02);
        ws = m0 * sx[ci];
    }

    // h==0 handles d = 2,4,6 ; h==1 handles d = 1,3,5
    #pragma unroll
    for (int k = 0; k < 3; ++k) {
        const int d = 2 * k + 2 - h;
        const float a1 = fmaf((float)(d * d), inv_den2, -c02);
        const float m  = bx_mask(a1);
        ws = fmaf(m, sx[ci - d] + sx[ci + d], ws);   // halo zero-padded
        if (INTERIOR) {
            sm += m;
        } else {
            const float cnt = (float)((f >= d) + (f + d < BX_F));
            dn = fmaf(m, cnt, dn);
        }
    }

    float den = INTERIOR ? fmaf(2.0f, sm, m0) : (dn + m0);

    // combine tap-parity halves
    ws  += __shfl_xor_sync(0xFFFFFFFFu, ws,  1);
    den += __shfl_xor_sync(0xFFFFFFFFu, den, 1);

    if (h == 0)
        out[row * BX_F + f] = ws * bx_rcp(den);
}

__global__ __launch_bounds__(BX_TPB)
void BumpX_kernel(const float* __restrict__ x,
                  const float* __restrict__ aa,
                  float* __restrict__ out)
{
    // blockIdx.x encodes (row, f-chunk): 16 chunks of 64 per row of F=1024
    const int row   = blockIdx.x >> 4;                 // b*L + l
    const int chunk = blockIdx.x & 15;
    const int fbase = chunk * BX_OPB;

    __shared__ float sx[BX_OPB + 2 * BX_W];            // 76 floats

    const float* xr = x + row * BX_F;

    // stage x[fbase-W .. fbase+OPB+W) with zero padding outside [0, F)
    for (int i = threadIdx.x; i < BX_OPB + 2 * BX_W; i += BX_TPB) {
        int g = fbase - BX_W + i;
        sx[i] = (g >= 0 && g < BX_F) ? xr[g] : 0.0f;
    }
    __syncthreads();

    if (chunk != 0 && chunk != 15)
        bx_body<true>(aa, out, sx, row, fbase);
    else
        bx_body<false>(aa, out, sx, row, fbase);
}

extern "C" void kernel_launch(void* const* d_in, const int* in_sizes, int n_in,
                              void* d_out, int out_size)
{
    const float* x  = (const float*)d_in[0];
    const float* aa = (const float*)d_in[1];
    float* out      = (float*)d_out;

    const int rows = out_size / BX_F;                  // B*L = 128
    dim3 grid(rows * (BX_F / BX_OPB));                 // 2048 blocks
    BumpX_kernel<<<grid, BX_TPB>>>(x, aa, out);
}

// round 6
// speedup vs baseline: 1.8037x; 1.1598x over previous
#include <cuda_runtime.h>
#include <cuda_bf16.h>

// BumpX: out[b,l,f] = sum_g mask(g-f, aa[b,l,f]) * x[b,l,g] / sum_g mask(...)
// mask(d,a) = 1 - gg((d^2 - a^2)/(6a+9)), gg(t)=ff(t)/(ff(t)+ff(1-t)),
// ff(t)=exp(-1/clamp(softplus(t),1e-6)).
//
// Math path (all single-MUFU SASS via inline PTX):
//   mask = 1/(1 + exp(1/v - 1/u)), u=softplus(arg), v=softplus(1-arg)
//   Lu = lg2(1+2^(arg*log2e)) = u/ln2,  Lv likewise
//   1/v - 1/u = log2e * (Lu-Lv)/(Lu*Lv)
//   mask = 0.5 - 0.5*tanh( 0.5*log2e * (Lu-Lv) * rcp(Lu*Lv) )   [MUFU.TANH]
//   => 6 MUFU per mask: ex2, ex2, lg2, lg2, rcp, tanh. tanh saturates to
//      exactly +-1 -> mask exactly 0/1, matching fp32 reference overflow.
//
// Structure:
//   * mask symmetric in d -> one mask per |d|; window |d|<=7 (dropped d>=8
//     taps have mask <= 4e-11 -> numerically identical to dense fp32).
//   * 2 threads per output: lane h=0 takes d={0,2,4,6}, h=1 takes d={1,3,5,7}
//     -> perfectly uniform 4-iteration loop, zero divergence. d=0 double
//     count fixed with weight 0.5. Combine with one shfl_xor.
//   * no smem, no __syncthreads: x taps via __ldg (x is L2-resident, L1-hot);
//     each warp depends only on its own loads.
//   * interior blocks (6/8 per row) compile away all boundary predicates.

#define BX_F    1024
#define BX_OPB  128         // outputs per block
#define BX_TPB  256         // 2 threads per output
#define BX_L2E   1.4426950408889634f
#define BX_HL2E  0.7213475204444817f   // 0.5 * log2e

__device__ __forceinline__ float bx_ex2(float x) {
    float r; asm("ex2.approx.ftz.f32 %0, %1;" : "=f"(r) : "f"(x)); return r;
}
__device__ __forceinline__ float bx_lg2(float x) {
    float r; asm("lg2.approx.ftz.f32 %0, %1;" : "=f"(r) : "f"(x)); return r;
}
__device__ __forceinline__ float bx_rcp(float x) {
    float r; asm("rcp.approx.ftz.f32 %0, %1;" : "=f"(r) : "f"(x)); return r;
}
__device__ __forceinline__ float bx_tanh(float x) {
    float r; asm("tanh.approx.f32 %0, %1;" : "=f"(r) : "f"(x)); return r;
}

__device__ __forceinline__ float bx_mask(float a1) {
    // a1 = arg * log2e
    float Lu = bx_lg2(1.0f + bx_ex2(a1));
    float Lv = bx_lg2(1.0f + bx_ex2(BX_L2E - a1));
    float q  = (Lu - Lv) * bx_rcp(Lu * Lv);
    return fmaf(-0.5f, bx_tanh(BX_HL2E * q), 0.5f);
}

template <bool INTERIOR>
__device__ __forceinline__ void bx_body(const float* __restrict__ x,
                                        const float* __restrict__ aa,
                                        float* __restrict__ out,
                                        int row, int fbase)
{
    const int o = (int)threadIdx.x >> 1;   // output within block
    const int h = (int)threadIdx.x & 1;    // tap-parity half

    const int f = fbase + o;
    const float* xr = x + row * BX_F;

    const float a        = __ldg(aa + row * BX_F + f);
    const float inv_den2 = BX_L2E * bx_rcp(fmaf(6.0f, a, 9.0f));
    const float c02      = a * a * inv_den2;   // (a^2/(6a+9)) * log2e

    float ws = 0.0f;    // weighted partial sum (this half)
    float dn = 0.0f;    // weighted mask sum   (this half)

    // h==0: d = 0,2,4,6 ; h==1: d = 1,3,5,7
    #pragma unroll
    for (int k = 0; k < 4; ++k) {
        const int   d  = 2 * k + h;
        const float w  = (d == 0) ? 0.5f : 1.0f;   // d=0 counted once
        const float a1 = fmaf((float)(d * d), inv_den2, -c02);
        const float mw = w * bx_mask(a1);

        if (INTERIOR) {
            ws = fmaf(mw, __ldg(xr + f - d) + __ldg(xr + f + d), ws);
            dn += mw;
        } else {
            const bool  lo = (f >= d);
            const bool  hi = (f + d < BX_F);
            const float xl = lo ? __ldg(xr + f - d) : 0.0f;
            const float xh = hi ? __ldg(xr + f + d) : 0.0f;
            ws = fmaf(mw, xl + xh, ws);
            dn = fmaf(mw, (float)((int)lo + (int)hi), dn);
        }
    }

    float den = INTERIOR ? (dn + dn) : dn;

    // combine tap-parity halves
    ws  += __shfl_xor_sync(0xFFFFFFFFu, ws,  1);
    den += __shfl_xor_sync(0xFFFFFFFFu, den, 1);

    if (h == 0)
        out[row * BX_F + f] = ws * bx_rcp(den);
}

__global__ __launch_bounds__(BX_TPB)
void BumpX_kernel(const float* __restrict__ x,
                  const float* __restrict__ aa,
                  float* __restrict__ out)
{
    // blockIdx.x encodes (row, f-chunk): 8 chunks of 128 per row of F=1024
    const int row   = blockIdx.x >> 3;                 // b*L + l
    const int chunk = blockIdx.x & 7;
    const int fbase = chunk * BX_OPB;

    if (chunk != 0 && chunk != 7)
        bx_body<true>(x, aa, out, row, fbase);
    else
        bx_body<false>(x, aa, out, row, fbase);
}

extern "C" void kernel_launch(void* const* d_in, const int* in_sizes, int n_in,
                              void* d_out, int out_size)
{
    const float* x  = (const float*)d_in[0];
    const float* aa = (const float*)d_in[1];
    float* out      = (float*)d_out;

    const int rows = out_size / BX_F;                  // B*L = 128
    dim3 grid(rows * (BX_F / BX_OPB));                 // 1024 blocks
    BumpX_kernel<<<grid, BX_TPB>>>(x, aa, out);
}

// round 7
// speedup vs baseline: 1.8287x; 1.0139x over previous
#include <cuda_runtime.h>
#include <cuda_bf16.h>

// BumpX: out[b,l,f] = sum_g mask(g-f, aa[b,l,f]) * x[b,l,g] / sum_g mask(...)
// mask(d,a) = 1 - gg(arg), arg = (d^2 - a^2)/(6a+9), gg(t)=ff(t)/(ff(t)+ff(1-t)),
// ff(t)=exp(-1/clamp(softplus(t),1e-6)).
//
// Round-7 idea: mask is a FIXED 1-D function of arg, and arg is bounded:
//   arg in (-1/15, 49/9]  (a in [0,1), |d| <= 7; taps |d|>=8 have mask <= 4e-11).
// So we bake a 512-entry lerp table of mask(arg) into the binary at COMPILE
// TIME (constexpr double-precision exp/log evaluating the exact reference
// formula, clamps included). The hot kernel does zero transcendentals per
// mask: fma -> fma -> cvt -> LDG.64 (8KB L1-resident) -> fma lerp.
// Lerp error ~3e-5 abs per tap vs the 1e-3 rel gate.
//
// Structure (unchanged from R6): 2 threads per output, lane h=0 takes
// d={0,2,4,6}, h=1 takes d={1,3,5,7}; d=0 weighted 0.5; shfl_xor combine;
// no smem/syncthreads; interior blocks drop boundary predicates.

#define BX_F    1024
#define BX_OPB  128
#define BX_TPB  256

#define BX_TAB_N 512
constexpr double BX_TAB_LO   = -0.08;
constexpr double BX_TAB_HI   =  5.52;
constexpr double BX_TAB_STEP = (BX_TAB_HI - BX_TAB_LO) / BX_TAB_N;  // 0.0109375
#define BX_INV_STEP 91.42857142857143f          // BX_TAB_N / (HI - LO)
#define BX_IDX_BIAS 7.314285714285714f          // -LO * INV_STEP

// ---------- compile-time math (double precision) ----------
constexpr double BX_LN2 = 0.6931471805599453;

constexpr double bx_cexp(double x) {            // x in [-95, 6]
    int n = (int)(x / BX_LN2 + (x >= 0.0 ? 0.5 : -0.5));
    double r = x - n * BX_LN2;                  // |r| <= ~0.347
    double s = 1.0, term = 1.0;
    for (int k = 1; k <= 12; ++k) { term *= r / k; s += term; }
    double p = 1.0;
    int m = n < 0 ? -n : n;
    for (int i = 0; i < m; ++i) p *= 2.0;
    return n < 0 ? s / p : s * p;
}
constexpr double bx_clog1p(double z) {          // z in (0, 1]
    double w = z / (z + 2.0);                   // w <= 1/3
    double w2 = w * w, s = 0.0, t = w;
    for (int k = 1; k <= 15; k += 2) { s += t / k; t *= w2; }
    return 2.0 * s;
}
constexpr double bx_csoftplus(double t) {
    double z = bx_cexp(t < 0.0 ? t : -t);
    double l = bx_clog1p(z);
    return (t > 0.0 ? t : 0.0) + l;
}
constexpr double bx_cmask(double arg) {         // exact reference formula
    double u = bx_csoftplus(arg);        if (u < 1e-6) u = 1e-6;
    double v = bx_csoftplus(1.0 - arg);  if (v < 1e-6) v = 1e-6;
    double f1 = bx_cexp(-1.0 / u);
    double f2 = bx_cexp(-1.0 / v);
    return f2 / (f1 + f2);                      // = 1 - gg(arg)
}

struct BxTab { float2 e[BX_TAB_N]; };           // e[i] = {m_i, m_{i+1}-m_i}

constexpr BxTab bx_make_tab() {
    BxTab T{};
    double prev = bx_cmask(BX_TAB_LO);
    for (int i = 0; i < BX_TAB_N; ++i) {
        double next = bx_cmask(BX_TAB_LO + (i + 1) * BX_TAB_STEP);
        T.e[i].x = (float)prev;
        T.e[i].y = (float)(next - prev);
        prev = next;
    }
    return T;
}

__device__ const BxTab bx_tab = bx_make_tab();  // constant-initialized, in GMEM

// ---------- runtime ----------
__device__ __forceinline__ float bx_rcp(float x) {
    float r; asm("rcp.approx.ftz.f32 %0, %1;" : "=f"(r) : "f"(x)); return r;
}

__device__ __forceinline__ float bx_mask_lut(float arg) {
    float tf   = fmaf(arg, BX_INV_STEP, BX_IDX_BIAS);   // >= 0, < 512
    int   i    = (int)tf;
    float frac = tf - (float)i;
    float2 e   = __ldg(&bx_tab.e[i]);
    return fmaf(frac, e.y, e.x);
}

template <bool INTERIOR>
__device__ __forceinline__ void bx_body(const float* __restrict__ x,
                                        const float* __restrict__ aa,
                                        float* __restrict__ out,
                                        int row, int fbase)
{
    const int o = (int)threadIdx.x >> 1;   // output within block
    const int h = (int)threadIdx.x & 1;    // tap-parity half

    const int f = fbase + o;
    const float* xr = x + row * BX_F;

    const float a       = __ldg(aa + row * BX_F + f);
    const float inv_den = bx_rcp(fmaf(6.0f, a, 9.0f));
    const float c0      = a * a * inv_den;          // a^2/(6a+9)

    float ws = 0.0f;
    float dn = 0.0f;

    // h==0: d = 0,2,4,6 ; h==1: d = 1,3,5,7
    #pragma unroll
    for (int k = 0; k < 4; ++k) {
        const int   d  = 2 * k + h;
        const float w  = (d == 0) ? 0.5f : 1.0f;    // d=0 counted once
        const float arg = fmaf((float)(d * d), inv_den, -c0);
        const float mw  = w * bx_mask_lut(arg);

        if (INTERIOR) {
            ws = fmaf(mw, __ldg(xr + f - d) + __ldg(xr + f + d), ws);
            dn += mw;
        } else {
            const bool  lo = (f >= d);
            const bool  hi = (f + d < BX_F);
            const float xl = lo ? __ldg(xr + f - d) : 0.0f;
            const float xh = hi ? __ldg(xr + f + d) : 0.0f;
            ws = fmaf(mw, xl + xh, ws);
            dn = fmaf(mw, (float)((int)lo + (int)hi), dn);
        }
    }

    float den = INTERIOR ? (dn + dn) : dn;

    ws  += __shfl_xor_sync(0xFFFFFFFFu, ws,  1);
    den += __shfl_xor_sync(0xFFFFFFFFu, den, 1);

    if (h == 0)
        out[row * BX_F + f] = ws * bx_rcp(den);
}

__global__ __launch_bounds__(BX_TPB)
void BumpX_kernel(const float* __restrict__ x,
                  const float* __restrict__ aa,
                  float* __restrict__ out)
{
    const int row   = blockIdx.x >> 3;              // b*L + l
    const int chunk = blockIdx.x & 7;
    const int fbase = chunk * BX_OPB;

    if (chunk != 0 && chunk != 7)
        bx_body<true>(x, aa, out, row, fbase);
    else
        bx_body<false>(x, aa, out, row, fbase);
}

extern "C" void kernel_launch(void* const* d_in, const int* in_sizes, int n_in,
                              void* d_out, int out_size)
{
    const float* x  = (const float*)d_in[0];
    const float* aa = (const float*)d_in[1];
    float* out      = (float*)d_out;

    const int rows = out_size / BX_F;               // B*L = 128
    dim3 grid(rows * (BX_F / BX_OPB));              // 1024 blocks
    BumpX_kernel<<<grid, BX_TPB>>>(x, aa, out);
}